// round 5
// baseline (speedup 1.0000x reference)
#include <cuda_runtime.h>

// InducingLocationsSpatialTransform: bilinear affine warp
// X: (N=512, H=64, W=64, C=32) f32, theta: (N, 6) f32 -> out: (N,H,W,C) f32
//
// 8 lanes per pixel (full 128B-line coalescing: minimal L1 wavefronts),
// 2 adjacent pixels per thread. __launch_bounds__(256,4) allows 64 regs so
// all 8 gather float4s are truly in flight (MLP=8) instead of being staged
// in batches by a 32-reg allocation.

#define N_ 512
#define H_ 64
#define W_ 64
#define C_ 32
#define HW_ (H_ * W_)

__global__ __launch_bounds__(256, 4) void st_kernel(
    const float* __restrict__ X,
    const float* __restrict__ theta,
    float* __restrict__ out)
{
    int tid = blockIdx.x * blockDim.x + threadIdx.x;
    int q   = tid >> 3;        // pixel-pair id; handles pixels 2q, 2q+1
    int cg  = tid & 7;         // float4 group within the 32 channels

    int pid0 = q << 1;         // even pixel
    int n = pid0 >> 12;        // image index
    int p = pid0 & 4095;
    int y = p >> 6;
    int x = p & 63;            // even

    const float* th = theta + n * 6;
    float t0 = __ldg(th + 0), t1 = __ldg(th + 1), t2 = __ldg(th + 2);
    float t3 = __ldg(th + 3), t4 = __ldg(th + 4), t5 = __ldg(th + 5);

    const float step = 2.0f / 63.0f;
    float xt = -1.0f + (float)x * step;
    float yt = -1.0f + (float)y * step;

    float gx0 = (float)W_ * ((t0 * xt + t1 * yt + t2) + 1.0f) * 0.5f;
    float gy0 = (float)H_ * ((t3 * xt + t4 * yt + t5) + 1.0f) * 0.5f;
    float gx1 = gx0 + (float)W_ * 0.5f * (t0 * step);
    float gy1 = gy0 + (float)H_ * 0.5f * (t3 * step);

    // ---- corner indices (needed before loads) ----
    float fx0 = floorf(gx0), fy0 = floorf(gy0);
    float fx1 = floorf(gx1), fy1 = floorf(gy1);
    int ax0 = min(max((int)fx0,     0), W_ - 1);
    int ax1 = min(max((int)fx0 + 1, 0), W_ - 1);
    int ay0 = min(max((int)fy0,     0), H_ - 1);
    int ay1 = min(max((int)fy0 + 1, 0), H_ - 1);
    int bx0 = min(max((int)fx1,     0), W_ - 1);
    int bx1 = min(max((int)fx1 + 1, 0), W_ - 1);
    int by0 = min(max((int)fy1,     0), H_ - 1);
    int by1 = min(max((int)fy1 + 1, 0), H_ - 1);

    const float4* S = (const float4*)(X + (size_t)n * HW_ * C_);

    // ---- issue all 8 independent loads back-to-back (MLP=8) ----
    float4 va0 = __ldg(&S[(ay0 * W_ + ax0) * 8 + cg]);
    float4 vb0 = __ldg(&S[(ay1 * W_ + ax0) * 8 + cg]);
    float4 vc0 = __ldg(&S[(ay0 * W_ + ax1) * 8 + cg]);
    float4 vd0 = __ldg(&S[(ay1 * W_ + ax1) * 8 + cg]);
    float4 va1 = __ldg(&S[(by0 * W_ + bx0) * 8 + cg]);
    float4 vb1 = __ldg(&S[(by1 * W_ + bx0) * 8 + cg]);
    float4 vc1 = __ldg(&S[(by0 * W_ + bx1) * 8 + cg]);
    float4 vd1 = __ldg(&S[(by1 * W_ + bx1) * 8 + cg]);

    // ---- weight math lives in the load shadow ----
    float wa0 = ((float)ax1 - gx0) * ((float)ay1 - gy0);
    float wb0 = ((float)ax1 - gx0) * (gy0 - (float)ay0);
    float wc0 = (gx0 - (float)ax0) * ((float)ay1 - gy0);
    float wd0 = (gx0 - (float)ax0) * (gy0 - (float)ay0);
    float wa1 = ((float)bx1 - gx1) * ((float)by1 - gy1);
    float wb1 = ((float)bx1 - gx1) * (gy1 - (float)by0);
    float wc1 = (gx1 - (float)bx0) * ((float)by1 - gy1);
    float wd1 = (gx1 - (float)bx0) * (gy1 - (float)by0);

    float4 r0, r1;
    r0.x = wa0 * va0.x + wb0 * vb0.x + wc0 * vc0.x + wd0 * vd0.x;
    r0.y = wa0 * va0.y + wb0 * vb0.y + wc0 * vc0.y + wd0 * vd0.y;
    r0.z = wa0 * va0.z + wb0 * vb0.z + wc0 * vc0.z + wd0 * vd0.z;
    r0.w = wa0 * va0.w + wb0 * vb0.w + wc0 * vc0.w + wd0 * vd0.w;
    r1.x = wa1 * va1.x + wb1 * vb1.x + wc1 * vc1.x + wd1 * vd1.x;
    r1.y = wa1 * va1.y + wb1 * vb1.y + wc1 * vc1.y + wd1 * vd1.y;
    r1.z = wa1 * va1.z + wb1 * vb1.z + wc1 * vc1.z + wd1 * vd1.z;
    r1.w = wa1 * va1.w + wb1 * vb1.w + wc1 * vc1.w + wd1 * vd1.w;

    float4* O = (float4*)out + (size_t)pid0 * 8;
    O[cg]     = r0;
    O[8 + cg] = r1;
}

extern "C" void kernel_launch(void* const* d_in, const int* in_sizes, int n_in,
                              void* d_out, int out_size)
{
    const float* X     = (const float*)d_in[0];
    const float* theta = (const float*)d_in[1];
    float* out         = (float*)d_out;

    int threads = 256;
    int blocks = (N_ * HW_ * 4) / threads;   // 32768
    st_kernel<<<blocks, threads>>>(X, theta, out);
}

// round 6
// speedup vs baseline: 1.1516x; 1.1516x over previous
#include <cuda_runtime.h>

// InducingLocationsSpatialTransform: bilinear affine warp
// X: (N=512, H=64, W=64, C=32) f32, theta: (N, 6) f32 -> out: (N,H,W,C) f32
//
// 8 lanes per pixel (full 128B-line coalescing), 2 adjacent pixels per
// thread. __launch_bounds__(256,6) caps at 42 regs -> 48 warps/SM (75% occ)
// while still fitting all 8 in-flight float4 gather payloads (MLP=8).
// Delta addressing (dx/dy offsets) trims the integer-address IMAD chains.

#define N_ 512
#define H_ 64
#define W_ 64
#define C_ 32
#define HW_ (H_ * W_)

__global__ __launch_bounds__(256, 6) void st_kernel(
    const float* __restrict__ X,
    const float* __restrict__ theta,
    float* __restrict__ out)
{
    int tid = blockIdx.x * blockDim.x + threadIdx.x;
    int q   = tid >> 3;        // pixel-pair id; handles pixels 2q, 2q+1
    int cg  = tid & 7;         // float4 group within the 32 channels

    int pid0 = q << 1;         // even pixel
    int n = pid0 >> 12;        // image index
    int p = pid0 & 4095;
    int y = p >> 6;
    int x = p & 63;            // even

    const float* th = theta + n * 6;
    float t0 = __ldg(th + 0), t1 = __ldg(th + 1), t2 = __ldg(th + 2);
    float t3 = __ldg(th + 3), t4 = __ldg(th + 4), t5 = __ldg(th + 5);

    const float step = 2.0f / 63.0f;
    float xt = -1.0f + (float)x * step;
    float yt = -1.0f + (float)y * step;

    float gx0 = (float)W_ * ((t0 * xt + t1 * yt + t2) + 1.0f) * 0.5f;
    float gy0 = (float)H_ * ((t3 * xt + t4 * yt + t5) + 1.0f) * 0.5f;
    float gx1 = gx0 + (float)W_ * 0.5f * (t0 * step);
    float gy1 = gy0 + (float)H_ * 0.5f * (t3 * step);

    // ---- corner indices ----
    float fx0 = floorf(gx0), fy0 = floorf(gy0);
    float fx1 = floorf(gx1), fy1 = floorf(gy1);
    int ax0 = min(max((int)fx0,     0), W_ - 1);
    int ax1 = min(max((int)fx0 + 1, 0), W_ - 1);
    int ay0 = min(max((int)fy0,     0), H_ - 1);
    int ay1 = min(max((int)fy0 + 1, 0), H_ - 1);
    int bx0 = min(max((int)fx1,     0), W_ - 1);
    int bx1 = min(max((int)fx1 + 1, 0), W_ - 1);
    int by0 = min(max((int)fy1,     0), H_ - 1);
    int by1 = min(max((int)fy1 + 1, 0), H_ - 1);

    const float4* S = (const float4*)(X + (size_t)n * HW_ * C_);

    // Delta addressing: one full address per pixel + cheap adds.
    int offA0 = ay0 * (W_ * 8) + ax0 * 8 + cg;     // (y0,x0)
    int dX0   = (ax1 - ax0) * 8;                   // 0 or 8
    int dY0   = (ay1 - ay0) * (W_ * 8);            // 0 or 512
    int offA1 = by0 * (W_ * 8) + bx0 * 8 + cg;
    int dX1   = (bx1 - bx0) * 8;
    int dY1   = (by1 - by0) * (W_ * 8);

    // ---- all 8 independent loads issued back-to-back (MLP=8) ----
    float4 va0 = __ldg(&S[offA0]);
    float4 vb0 = __ldg(&S[offA0 + dY0]);
    float4 vc0 = __ldg(&S[offA0 + dX0]);
    float4 vd0 = __ldg(&S[offA0 + dX0 + dY0]);
    float4 va1 = __ldg(&S[offA1]);
    float4 vb1 = __ldg(&S[offA1 + dY1]);
    float4 vc1 = __ldg(&S[offA1 + dX1]);
    float4 vd1 = __ldg(&S[offA1 + dX1 + dY1]);

    // ---- weight math in the load shadow ----
    float wa0 = ((float)ax1 - gx0) * ((float)ay1 - gy0);
    float wb0 = ((float)ax1 - gx0) * (gy0 - (float)ay0);
    float wc0 = (gx0 - (float)ax0) * ((float)ay1 - gy0);
    float wd0 = (gx0 - (float)ax0) * (gy0 - (float)ay0);
    float wa1 = ((float)bx1 - gx1) * ((float)by1 - gy1);
    float wb1 = ((float)bx1 - gx1) * (gy1 - (float)by0);
    float wc1 = (gx1 - (float)bx0) * ((float)by1 - gy1);
    float wd1 = (gx1 - (float)bx0) * (gy1 - (float)by0);

    float4 r0, r1;
    r0.x = wa0 * va0.x + wb0 * vb0.x + wc0 * vc0.x + wd0 * vd0.x;
    r0.y = wa0 * va0.y + wb0 * vb0.y + wc0 * vc0.y + wd0 * vd0.y;
    r0.z = wa0 * va0.z + wb0 * vb0.z + wc0 * vc0.z + wd0 * vd0.z;
    r0.w = wa0 * va0.w + wb0 * vb0.w + wc0 * vc0.w + wd0 * vd0.w;
    r1.x = wa1 * va1.x + wb1 * vb1.x + wc1 * vc1.x + wd1 * vd1.x;
    r1.y = wa1 * va1.y + wb1 * vb1.y + wc1 * vc1.y + wd1 * vd1.y;
    r1.z = wa1 * va1.z + wb1 * vb1.z + wc1 * vc1.z + wd1 * vd1.z;
    r1.w = wa1 * va1.w + wb1 * vb1.w + wc1 * vc1.w + wd1 * vd1.w;

    float4* O = (float4*)out + (size_t)pid0 * 8;
    O[cg]     = r0;
    O[8 + cg] = r1;
}

extern "C" void kernel_launch(void* const* d_in, const int* in_sizes, int n_in,
                              void* d_out, int out_size)
{
    const float* X     = (const float*)d_in[0];
    const float* theta = (const float*)d_in[1];
    float* out         = (float*)d_out;

    int threads = 256;
    int blocks = (N_ * HW_ * 4) / threads;   // 32768
    st_kernel<<<blocks, threads>>>(X, theta, out);
}